// round 10
// baseline (speedup 1.0000x reference)
#include <cuda_runtime.h>
#include <cuda_fp16.h>
#include <cstdint>

// ------------- problem constants -------------
#define CIN   128
#define COUT  256
#define HIN   56
#define WIN   56
#define HOUT  54
#define WOUT  54
#define NPIX  (HOUT*WOUT)
#define BATCH 64
#define TPI   729                 // 27x27 winograd tiles per image
#define NTILES (BATCH*TPI)        // 46656
#define NW    (COUT*CIN*9)

// GEMM smem: 2 stages x (A 64x272B + B 128x272B); epilogue reuses as f32x4 [128][65]
#define ROWB  272
#define A_SM  (64*ROWB)           // 17408
#define B_SM  (128*ROWB)          // 34816
#define STG   (A_SM + B_SM)       // 52224
#define EPS   65                  // epilogue float4 stride (conflict-free)
#define SM_TOTAL 135168

// ------------- device scratch -------------
__device__ int g_max_bits = 0;    // idempotent across replays (same inputs)
__device__ __align__(256) __half g_xh[(size_t)BATCH*HIN*WIN*CIN];  // NHWC fp16
__device__ __align__(256) __half g_V[(size_t)NTILES*16*CIN];       // [tile][pos][ci]
__device__ __align__(256) __half g_wu[16*COUT*CIN];                // [pos][co][ci]

// ------------- helpers -------------
__device__ __forceinline__ uint32_t smem_u32(const void* p) {
    uint32_t a;
    asm("{ .reg .u64 t; cvta.to.shared.u64 t, %1; cvt.u32.u64 %0, t; }"
        : "=r"(a) : "l"(p));
    return a;
}
__device__ __forceinline__ void cpa16(uint32_t dst, const void* src) {
    asm volatile("cp.async.cg.shared.global [%0], [%1], 16;"
                 :: "r"(dst), "l"(src) : "memory");
}
__device__ __forceinline__ void cpa_commit() {
    asm volatile("cp.async.commit_group;" ::: "memory");
}
template <int N>
__device__ __forceinline__ void cpa_wait() {
    asm volatile("cp.async.wait_group %0;" :: "n"(N) : "memory");
}
__device__ __forceinline__ void ldsm4(uint32_t* r, uint32_t a) {
    asm volatile("ldmatrix.sync.aligned.m8n8.x4.shared.b16 {%0,%1,%2,%3}, [%4];"
                 : "=r"(r[0]), "=r"(r[1]), "=r"(r[2]), "=r"(r[3]) : "r"(a));
}
__device__ __forceinline__ void mma16816(float* d, const uint32_t* a, const uint32_t* b) {
    asm volatile(
        "mma.sync.aligned.m16n8k16.row.col.f32.f16.f16.f32 "
        "{%0,%1,%2,%3}, {%4,%5,%6,%7}, {%8,%9}, {%0,%1,%2,%3};"
        : "+f"(d[0]), "+f"(d[1]), "+f"(d[2]), "+f"(d[3])
        : "r"(a[0]), "r"(a[1]), "r"(a[2]), "r"(a[3]), "r"(b[0]), "r"(b[1]));
}

// ---------------- kernel 1: max |w| ----------------
__global__ void maxabs_kernel(const float* __restrict__ w, int n) {
    float m = 0.f;
    for (int i = blockIdx.x * blockDim.x + threadIdx.x; i < n; i += gridDim.x * blockDim.x)
        m = fmaxf(m, fabsf(w[i]));
#pragma unroll
    for (int o = 16; o; o >>= 1) m = fmaxf(m, __shfl_xor_sync(0xffffffffu, m, o));
    __shared__ float sm[8];
    int lane = threadIdx.x & 31, wid = threadIdx.x >> 5;
    if (lane == 0) sm[wid] = m;
    __syncthreads();
    if (wid == 0) {
        m = (lane < 8) ? sm[lane] : 0.f;
#pragma unroll
        for (int o = 4; o; o >>= 1) m = fmaxf(m, __shfl_xor_sync(0xffffffffu, m, o));
        if (lane == 0) atomicMax(&g_max_bits, __float_as_int(m));
    }
}

// ---------------- kernel 2: quantize + winograd weight transform ----------------
__global__ void __launch_bounds__(128)
wtrans_kernel(const float* __restrict__ w,
              const float* __restrict__ wp,
              const float* __restrict__ wn) {
    __shared__ __align__(16) __half stg[16][128];
    const int co = blockIdx.x, ci = threadIdx.x;
    const float t   = 0.05f * __int_as_float(g_max_bits);
    const float wpa = fabsf(wp[0]);
    const float wna = fabsf(wn[0]);
    const float* g = w + ((size_t)co * CIN + ci) * 9;
    float q[9];
#pragma unroll
    for (int k = 0; k < 9; ++k) {
        float v = g[k];
        q[k] = (v > t) ? wpa : ((v < -t) ? -wna : 0.f);
    }
    float T[4][3];
#pragma unroll
    for (int c = 0; c < 3; ++c) {
        T[0][c] = q[c];
        T[1][c] = 0.5f * (q[c] + q[3 + c] + q[6 + c]);
        T[2][c] = 0.5f * (q[c] - q[3 + c] + q[6 + c]);
        T[3][c] = q[6 + c];
    }
#pragma unroll
    for (int r = 0; r < 4; ++r) {
        float u0 = T[r][0];
        float u1 = 0.5f * (T[r][0] + T[r][1] + T[r][2]);
        float u2 = 0.5f * (T[r][0] - T[r][1] + T[r][2]);
        float u3 = T[r][2];
        stg[r * 4 + 0][ci] = __float2half_rn(u0);
        stg[r * 4 + 1][ci] = __float2half_rn(u1);
        stg[r * 4 + 2][ci] = __float2half_rn(u2);
        stg[r * 4 + 3][ci] = __float2half_rn(u3);
    }
    __syncthreads();
#pragma unroll
    for (int k = 0; k < 2; ++k) {
        int chunk = k * 128 + threadIdx.x;
        int pos = chunk >> 4, off = chunk & 15;
        ((uint4*)(g_wu + ((size_t)(pos * COUT + co)) * CIN))[off] =
            ((const uint4*)&stg[pos][0])[off];
    }
}

// ---------------- kernel 3: x NCHW f32 -> NHWC f16 ----------------
__global__ void __launch_bounds__(256)
transpose_kernel(const float* __restrict__ x) {
    __shared__ __half tile[WIN * 130];
    int b = blockIdx.x / HIN, y = blockIdx.x % HIN;
    const float* src = x + ((size_t)b * CIN) * (HIN * WIN) + y * WIN;
    for (int i = threadIdx.x; i < CIN * WIN; i += 256) {
        int ci = i / WIN, xx = i - ci * WIN;
        tile[xx * 130 + ci] = __float2half_rn(src[(size_t)ci * (HIN * WIN) + xx]);
    }
    __syncthreads();
    __half* dst = g_xh + ((size_t)(b * HIN + y) * WIN) * CIN;
    for (int i = threadIdx.x; i < CIN * WIN; i += 256) {
        int xx = i >> 7, ci = i & 127;
        dst[i] = tile[xx * 130 + ci];
    }
}

// ---------------- kernel 4: input transform V = B^T d B ----------------
__global__ void __launch_bounds__(256)
itrans_kernel() {
    __shared__ __align__(16) __half stg[2][16][128];
    const int tl = threadIdx.x >> 7, ci = threadIdx.x & 127;
    const int tile = blockIdx.x * 2 + tl;
    const int b = tile / TPI;
    const int r = tile - b * TPI;
    const int ty = r / 27, tx = r - ty * 27;
    const __half* src = g_xh + ((size_t)((b * HIN + 2 * ty) * WIN + 2 * tx)) * CIN + ci;
    float d[4][4];
#pragma unroll
    for (int yy = 0; yy < 4; ++yy)
#pragma unroll
        for (int xx = 0; xx < 4; ++xx)
            d[yy][xx] = __half2float(src[(size_t)(yy * WIN + xx) * CIN]);
    float tm[4][4];
#pragma unroll
    for (int c = 0; c < 4; ++c) {
        tm[0][c] = d[0][c] - d[2][c];
        tm[1][c] = d[1][c] + d[2][c];
        tm[2][c] = d[2][c] - d[1][c];
        tm[3][c] = d[1][c] - d[3][c];
    }
#pragma unroll
    for (int rr = 0; rr < 4; ++rr) {
        float v0 = tm[rr][0] - tm[rr][2];
        float v1 = tm[rr][1] + tm[rr][2];
        float v2 = tm[rr][2] - tm[rr][1];
        float v3 = tm[rr][1] - tm[rr][3];
        stg[tl][rr * 4 + 0][ci] = __float2half_rn(v0);
        stg[tl][rr * 4 + 1][ci] = __float2half_rn(v1);
        stg[tl][rr * 4 + 2][ci] = __float2half_rn(v2);
        stg[tl][rr * 4 + 3][ci] = __float2half_rn(v3);
    }
    __syncthreads();
    uint4* d4 = (uint4*)(g_V + (size_t)blockIdx.x * 2 * 16 * CIN);
    const uint4* s4 = (const uint4*)&stg[0][0][0];
    d4[threadIdx.x]       = s4[threadIdx.x];
    d4[threadIdx.x + 256] = s4[threadIdx.x + 256];
}

// ---------------- winograd GEMM pos-step (compile-time facc buffers) ----------------
__device__ __forceinline__ void wg_pos_step(
    int pos, uint32_t soff,
    const uint32_t* aoff, const uint32_t* boff,
    float (&fw)[2][4][4], float (&ft)[2][4][4],
    float (&oacc)[2][4][4][4], bool dot)
{
    float w00 = 0.f, w01 = 0.f, w10 = 0.f, w11 = 0.f;
    if (dot) {                       // coefficients of pos-1
        const int pv = pos - 1, p = pv >> 2, q = pv & 3;
        const float cp0 = (p == 3) ? 0.f : 1.f;
        const float cp1 = (p == 0) ? 0.f : ((p == 1) ? 1.f : -1.f);
        const float cq0 = (q == 3) ? 0.f : 1.f;
        const float cq1 = (q == 0) ? 0.f : ((q == 1) ? 1.f : -1.f);
        w00 = cp0 * cq0; w01 = cp0 * cq1; w10 = cp1 * cq0; w11 = cp1 * cq1;
    }
#pragma unroll
    for (int mf = 0; mf < 2; ++mf)
#pragma unroll
        for (int nf = 0; nf < 4; ++nf)
#pragma unroll
            for (int e = 0; e < 4; ++e) fw[mf][nf][e] = 0.f;

#pragma unroll
    for (int ks = 0; ks < 8; ++ks) {
        uint32_t afr[2][4], bfr[2][4];
        ldsm4(afr[0], aoff[0] + soff + ks * 32);
        ldsm4(afr[1], aoff[1] + soff + ks * 32);
        ldsm4(bfr[0], boff[0] + soff + ks * 32);
        ldsm4(bfr[1], boff[1] + soff + ks * 32);
#pragma unroll
        for (int mf = 0; mf < 2; ++mf)
#pragma unroll
            for (int nf = 0; nf < 4; ++nf)
                mma16816(fw[mf][nf], afr[mf], &bfr[nf >> 1][(nf & 1) * 2]);
        if (dot) {                   // interleaved transform of PREVIOUS pos
            const int mf = ks >> 2, nf = ks & 3;
#pragma unroll
            for (int e = 0; e < 4; ++e) {
                const float f = ft[mf][nf][e];
                oacc[mf][nf][e][0] += w00 * f;
                oacc[mf][nf][e][1] += w01 * f;
                oacc[mf][nf][e][2] += w10 * f;
                oacc[mf][nf][e][3] += w11 * f;
            }
        }
    }
}

// ---------------- kernel 5: winograd GEMM + deferred fused output transform ----------------
__global__ void __launch_bounds__(256, 1)
wg_gemm_kernel(const float* __restrict__ bias, float* __restrict__ out) {
    extern __shared__ char smem[];
    const uint32_t sb = smem_u32(smem);
    const int tid = threadIdx.x;
    const int wid = tid >> 5, lane = tid & 31;
    const int m0t = blockIdx.x * 64;       // tile base
    const int n0  = blockIdx.y * 128;      // cout base

    // warp grid 2(m) x 4(n); warp tile 32(m) x 32(n)
    const int wm = (wid & 1) * 32;
    const int wn = (wid >> 1) * 32;

    // A producer: 64 rows x 256B, each thread 64B
    const char* asrcB = (const char*)g_V
        + (size_t)(m0t + (tid >> 2)) * 4096 + (tid & 3) * 64;
    const uint32_t adst = sb + (uint32_t)(tid >> 2) * ROWB + (tid & 3) * 64;
    // B producer: 128 rows x 256B, each thread 128B
    const char* bsrcB = (const char*)g_wu
        + (size_t)(n0 + (tid >> 1)) * 256 + (tid & 1) * 128;
    const uint32_t bdst = sb + A_SM + (uint32_t)(tid >> 1) * ROWB + (tid & 1) * 128;

    // ldmatrix bases
    uint32_t aoff[2], boff[2];
#pragma unroll
    for (int mf = 0; mf < 2; ++mf)
        aoff[mf] = sb + (uint32_t)(wm + mf * 16 + (lane & 15)) * ROWB
                 + ((lane >> 4) ? 16u : 0u);
#pragma unroll
    for (int h = 0; h < 2; ++h)
        boff[h] = sb + A_SM
                + (uint32_t)(wn + h * 16 + ((lane >> 4) << 3) + (lane & 7)) * ROWB
                + (((lane >> 3) & 1) ? 16u : 0u);

    float oacc[2][4][4][4];
#pragma unroll
    for (int mf = 0; mf < 2; ++mf)
#pragma unroll
        for (int nf = 0; nf < 4; ++nf)
#pragma unroll
            for (int e = 0; e < 4; ++e)
#pragma unroll
                for (int o = 0; o < 4; ++o) oacc[mf][nf][e][o] = 0.f;

    float facc0[2][4][4], facc1[2][4][4];

    // prefetch pos 0 into stage 0
    {
#pragma unroll
        for (int c = 0; c < 4; ++c) cpa16(adst + c * 16, asrcB + c * 16);
#pragma unroll
        for (int c = 0; c < 8; ++c) cpa16(bdst + c * 16, bsrcB + c * 16);
        cpa_commit();
    }

#pragma unroll 1
    for (int pp = 0; pp < 8; ++pp) {
        const int pe = 2 * pp;          // even pos -> writes facc0, transforms facc1
        cpa_wait<0>();
        __syncthreads();
        {   // prefetch pe+1 into stage 1
            const char* as = asrcB + (pe + 1) * 256;
            const char* bs = bsrcB + (size_t)(pe + 1) * (COUT * 256);
#pragma unroll
            for (int c = 0; c < 4; ++c) cpa16(adst + STG + c * 16, as + c * 16);
#pragma unroll
            for (int c = 0; c < 8; ++c) cpa16(bdst + STG + c * 16, bs + c * 16);
            cpa_commit();
        }
        wg_pos_step(pe, 0, aoff, boff, facc0, facc1, oacc, pe > 0);

        const int po = pe + 1;          // odd pos -> writes facc1, transforms facc0
        cpa_wait<0>();
        __syncthreads();
        if (po + 1 < 16) {              // prefetch po+1 into stage 0
            const char* as = asrcB + (po + 1) * 256;
            const char* bs = bsrcB + (size_t)(po + 1) * (COUT * 256);
#pragma unroll
            for (int c = 0; c < 4; ++c) cpa16(adst + c * 16, as + c * 16);
#pragma unroll
            for (int c = 0; c < 8; ++c) cpa16(bdst + c * 16, bs + c * 16);
        }
        cpa_commit();
        wg_pos_step(po, STG, aoff, boff, facc1, facc0, oacc, true);
    }
    // final transform for pos 15 (p=3,q=3): only w11 = 1
#pragma unroll
    for (int mf = 0; mf < 2; ++mf)
#pragma unroll
        for (int nf = 0; nf < 4; ++nf)
#pragma unroll
            for (int e = 0; e < 4; ++e)
                oacc[mf][nf][e][3] += facc1[mf][nf][e];

    __syncthreads();                    // mainloop smem reads done

    // stage 2x2 outputs: ep4[co][tile] with padded stride EPS
    float4* ep4 = (float4*)smem;
    {
        const int quad = lane >> 2, tq = lane & 3;
#pragma unroll
        for (int mf = 0; mf < 2; ++mf)
#pragma unroll
            for (int nf = 0; nf < 4; ++nf)
#pragma unroll
                for (int e = 0; e < 4; ++e) {
                    const int m_l  = wm + mf * 16 + quad + 8 * (e >> 1);
                    const int co_l = wn + nf * 8 + tq * 2 + (e & 1);
                    ep4[co_l * EPS + m_l] = make_float4(
                        oacc[mf][nf][e][0], oacc[mf][nf][e][1],
                        oacc[mf][nf][e][2], oacc[mf][nf][e][3]);
                }
    }
    __syncthreads();

    // writer: 2x2 pixels per (tile, co), + bias
    {
        const int m = tid & 63, grp = tid >> 6;   // 4 groups x 32 co
        const int tg = m0t + m;
        const int b = tg / TPI;
        const int rr = tg - b * TPI;
        const int ty = rr / 27, tx = rr - ty * 27;
        float* ob = out + (size_t)b * COUT * NPIX + (2 * ty) * WOUT + 2 * tx;
#pragma unroll
        for (int cc = 0; cc < 32; ++cc) {
            const int co_l = grp * 32 + cc;
            float4 v = ep4[co_l * EPS + m];
            const float bv = __ldg(bias + n0 + co_l);
            float* pp = ob + (size_t)(n0 + co_l) * NPIX;
            *(float2*)pp          = make_float2(v.x + bv, v.y + bv);
            *(float2*)(pp + WOUT) = make_float2(v.z + bv, v.w + bv);
        }
    }
}

// ---------------- launch ----------------
extern "C" void kernel_launch(void* const* d_in, const int* in_sizes, int n_in,
                              void* d_out, int out_size) {
    const float* x    = (const float*)d_in[0];
    const float* w    = (const float*)d_in[1];
    const float* bias = (const float*)d_in[2];
    const float* wp   = (const float*)d_in[3];
    const float* wn   = (const float*)d_in[4];
    float* out = (float*)d_out;

    maxabs_kernel<<<256, 256>>>(w, NW);
    wtrans_kernel<<<COUT, 128>>>(w, wp, wn);
    transpose_kernel<<<BATCH * HIN, 256>>>(x);
    itrans_kernel<<<NTILES / 2, 256>>>();

    cudaFuncSetAttribute(wg_gemm_kernel,
                         cudaFuncAttributeMaxDynamicSharedMemorySize, SM_TOTAL);
    dim3 grid(NTILES / 64, COUT / 128);   // 729 x 2
    wg_gemm_kernel<<<grid, 256, SM_TOTAL>>>(bias, out);
}